// round 4
// baseline (speedup 1.0000x reference)
#include <cuda_runtime.h>
#include <math.h>
#include <float.h>

#define HH 496
#define WW 496
#define NC 9          // sigma x lambda combos
#define NT 8          // thetas
#define NW 31         // windows per dim (496/16)
#define NWIN (NW*NW)  // 961
#define NCOEF (NT*NC*25)

// ---- scratch (static device globals; no allocation) ----
__device__ float gCoef[NCOEF];          // [t][c][25]
__device__ float gOut[NC*HH*WW];        // conv+max result, 8.86 MB
__device__ float gPartial[NC*NWIN];     // per-block channel sums
__device__ float gThr5[NC];             // mean*5 per channel
__device__ int   gValid[NWIN];          // valid_kp per window

__device__ __constant__ float dThetas[8] = {
    0.39269908169872414f, 0.7853981633974483f, 1.1780972450961724f,
    1.5707963267948966f,  1.9634954084936207f, 2.356194490192345f,
    2.748893571891069f,   3.141592653589793f
};

// ============ Kernel 1: Gabor bank ============
__global__ void gabor_kernel(const float* __restrict__ sigmas,
                             const float* __restrict__ lambdas) {
    int i = blockIdx.x * blockDim.x + threadIdx.x;
    if (i >= NCOEF) return;
    int k = i % 25;
    int c = (i / 25) % NC;
    int t = i / (25 * NC);
    int s = c / 3, l = c % 3;
    float sig = sigmas[s];
    float lam = lambdas[l];
    float th  = dThetas[t];
    int ky = k / 5, kx = k % 5;
    float y = (float)ky - 2.0f;
    float x = (float)kx - 2.0f;
    float st = sinf(th), ct = cosf(th);
    float yth = -x * st + y * ct;
    float xth =  x * ct + y * st;
    float sx = sig;          // sigma_x
    float sy = 2.0f * sig;   // sigma_y = sigma/gamma, gamma=0.5
    float e = expf(-0.5f * (xth*xth/(sx*sx) + yth*yth/(sy*sy)));
    float g = e * cosf(6.283185307179586f * xth / lam + 1.5707963267948966f);
    gCoef[(t * NC + c) * 25 + k] = g;
}

// ============ Kernel 2: conv (72 filters) + max over theta + block sums ====
// 31x31 blocks of 64 threads; 16x16 output tile; thread = 4 horizontal pixels.
__global__ void __launch_bounds__(64)
conv_kernel(const float* __restrict__ img) {
    __shared__ float sIn[20 * 20];
    __shared__ float sCf[NCOEF];
    __shared__ float sSum[NC * 64];

    int tid = threadIdx.x;
    int bx = blockIdx.x, by = blockIdx.y;
    int r0 = by * 16 - 2, c0 = bx * 16 - 2;

    // halo'd input tile (zero pad)
    for (int i = tid; i < 400; i += 64) {
        int r = i / 20, cc = i % 20;
        int gr = r0 + r, gc = c0 + cc;
        sIn[i] = (gr >= 0 && gr < HH && gc >= 0 && gc < WW) ? img[gr * WW + gc] : 0.0f;
    }
    for (int i = tid; i < NCOEF; i += 64) sCf[i] = gCoef[i];
    __syncthreads();

    int ty = tid >> 2;            // 0..15
    int tx = (tid & 3) * 4;       // 0,4,8,12

    float vin[5][8];
    #pragma unroll
    for (int r = 0; r < 5; r++)
        #pragma unroll
        for (int cc = 0; cc < 8; cc++)
            vin[r][cc] = sIn[(ty + r) * 20 + tx + cc];

    float vmax[4][NC];
    #pragma unroll
    for (int p = 0; p < 4; p++)
        #pragma unroll
        for (int c = 0; c < NC; c++) vmax[p][c] = -FLT_MAX;

    for (int t = 0; t < NT; t++) {
        const float* cf = sCf + t * NC * 25;
        #pragma unroll
        for (int c = 0; c < NC; c++) {
            float a0 = 0.0f, a1 = 0.0f, a2 = 0.0f, a3 = 0.0f;
            #pragma unroll
            for (int k = 0; k < 25; k++) {
                int ky = k / 5, kx = k % 5;
                float w = cf[c * 25 + k];
                a0 = fmaf(w, vin[ky][kx + 0], a0);
                a1 = fmaf(w, vin[ky][kx + 1], a1);
                a2 = fmaf(w, vin[ky][kx + 2], a2);
                a3 = fmaf(w, vin[ky][kx + 3], a3);
            }
            vmax[0][c] = fmaxf(vmax[0][c], a0);
            vmax[1][c] = fmaxf(vmax[1][c], a1);
            vmax[2][c] = fmaxf(vmax[2][c], a2);
            vmax[3][c] = fmaxf(vmax[3][c], a3);
        }
    }

    int gy = by * 16 + ty;
    int gx = bx * 16 + tx;
    #pragma unroll
    for (int c = 0; c < NC; c++) {
        float4 o = make_float4(vmax[0][c], vmax[1][c], vmax[2][c], vmax[3][c]);
        *(float4*)&gOut[c * HH * WW + gy * WW + gx] = o;
        sSum[c * 64 + tid] = vmax[0][c] + vmax[1][c] + vmax[2][c] + vmax[3][c];
    }
    __syncthreads();
    // deterministic tree reduce (no fp atomics!)
    for (int off = 32; off >= 1; off >>= 1) {
        if (tid < off) {
            #pragma unroll
            for (int c = 0; c < NC; c++)
                sSum[c * 64 + tid] += sSum[c * 64 + tid + off];
        }
        __syncthreads();
    }
    if (tid == 0) {
        int b = by * NW + bx;
        #pragma unroll
        for (int c = 0; c < NC; c++)
            gPartial[c * NWIN + b] = sSum[c * 64];
    }
}

// ============ Kernel 3: deterministic mean -> thr5 ============
__global__ void mean_kernel() {
    int tid = threadIdx.x;
    int c = tid >> 5, lane = tid & 31;
    if (c >= NC) return;
    float s = 0.0f;
    for (int i = lane; i < NWIN; i += 32) s += gPartial[c * NWIN + i];
    #pragma unroll
    for (int off = 16; off; off >>= 1)
        s += __shfl_down_sync(0xffffffff, s, off);
    if (lane == 0)
        gThr5[c] = (s / (float)(HH * WW)) * 5.0f;
}

// ============ Kernel 4: per-window argmax (first occurrence) -> valid ======
// 961 blocks x 288 threads; warp c handles channel c of window w.
__global__ void argmax_kernel() {
    __shared__ int sFlag[NC];
    int w = blockIdx.x;
    int tid = threadIdx.x;
    int c = tid >> 5, lane = tid & 31;
    int R = (w / NW) * 16, C = (w % NW) * 16;
    float thr5 = gThr5[c];
    const float* o = gOut + c * HH * WW;

    float best = -FLT_MAX;
    int bidx = 256;
    #pragma unroll
    for (int k = 0; k < 8; k++) {
        int f = lane * 8 + k;           // flat index within 16x16, ascending
        int i = f >> 4, j = f & 15;
        float v = o[(R + i) * WW + C + j];
        float tv = (v > thr5) ? v : 0.0f;
        if (tv > best) { best = tv; bidx = f; }   // strict > keeps first
    }
    #pragma unroll
    for (int off = 16; off; off >>= 1) {
        float ov = __shfl_xor_sync(0xffffffff, best, off);
        int   oi = __shfl_xor_sync(0xffffffff, bidx, off);
        if (ov > best || (ov == best && oi < bidx)) { best = ov; bidx = oi; }
    }
    if (lane == 0) sFlag[c] = (bidx == 128);
    __syncthreads();
    if (tid == 0) {
        int v = 0;
        #pragma unroll
        for (int k = 0; k < NC; k++) v |= sFlag[k];
        gValid[w] = v;
    }
}

// ============ Kernel 5: patches (load, nonzero-any, masked write) ==========
// grid (961, 9), 256 threads, 4 elems/thread, float4 stores.
__global__ void patch_kernel(float* __restrict__ dst) {
    __shared__ int sNz[8];
    __shared__ int sMask;
    int w = blockIdx.x, c = blockIdx.y;
    int tid = threadIdx.x;
    int wr = (w / NW) * 16 - 8;   // real top row of 32x32 patch
    int wc = (w % NW) * 16 - 8;
    const float* o = gOut + c * HH * WW;

    int base = tid * 4;
    int i = base >> 5, j0 = base & 31;
    int rr = wr + i;
    bool rok = (rr >= 0 && rr < HH);
    float v[4];
    #pragma unroll
    for (int e = 0; e < 4; e++) {
        int cc = wc + j0 + e;
        v[e] = (rok && cc >= 0 && cc < WW) ? o[rr * WW + cc] : 0.0f;
    }
    int nz = (v[0] != 0.0f) | (v[1] != 0.0f) | (v[2] != 0.0f) | (v[3] != 0.0f);
    unsigned bal = __ballot_sync(0xffffffff, nz);
    if ((tid & 31) == 0) sNz[tid >> 5] = (bal != 0);
    __syncthreads();
    if (tid == 0) {
        int a = 0;
        #pragma unroll
        for (int k = 0; k < 8; k++) a |= sNz[k];
        sMask = a && gValid[w];
    }
    __syncthreads();
    float m = sMask ? 1.0f : 0.0f;
    float4 ov = make_float4(v[0] * m, v[1] * m, v[2] * m, v[3] * m);
    ((float4*)dst)[(c * NWIN + w) * 256 + tid] = ov;
}

// ============ launcher ============
extern "C" void kernel_launch(void* const* d_in, const int* in_sizes, int n_in,
                              void* d_out, int out_size) {
    const float* img     = (const float*)d_in[0];
    const float* sigmas  = (const float*)d_in[1];
    const float* lambdas = (const float*)d_in[2];
    float* out = (float*)d_out;

    gabor_kernel<<<(NCOEF + 255) / 256, 256>>>(sigmas, lambdas);
    conv_kernel<<<dim3(NW, NW), 64>>>(img);
    mean_kernel<<<1, 288>>>();
    argmax_kernel<<<NWIN, 288>>>();
    patch_kernel<<<dim3(NWIN, NC), 256>>>(out);
}